// round 1
// baseline (speedup 1.0000x reference)
#include <cuda_runtime.h>
#include <cuda_bf16.h>

// Grouping: out[B,G,H] = sum_{t=0..3} values[(b*G+g)*4+t] * feats[b, g*4+t, :]
// B=8, S=4096, H=1024, G=1024, TOKENS_PER_GROUP=4.
// nnz entries are ordered b-major then s; group g covers tokens [4g, 4g+4).
// Flattened: output row r in [0, B*G) reads feats rows 4r..4r+3 and values 4r..4r+3.

static constexpr int H_VEC = 1024 / 4;  // 256 float4 per row

__global__ __launch_bounds__(256, 8)
void grouping_kernel(const float4* __restrict__ feats,
                     const float* __restrict__ values,
                     float4* __restrict__ out) {
    const int r = blockIdx.x;            // output row: b*G + g
    const int c = threadIdx.x;           // float4 column, 0..255

    const size_t src_base = (size_t)r * 4 * H_VEC;
    const float v0 = __ldg(&values[4 * r + 0]);
    const float v1 = __ldg(&values[4 * r + 1]);
    const float v2 = __ldg(&values[4 * r + 2]);
    const float v3 = __ldg(&values[4 * r + 3]);

    // 4 independent 16B loads -> MLP=4 per thread
    const float4 a = __ldg(&feats[src_base + 0 * H_VEC + c]);
    const float4 b = __ldg(&feats[src_base + 1 * H_VEC + c]);
    const float4 d = __ldg(&feats[src_base + 2 * H_VEC + c]);
    const float4 e = __ldg(&feats[src_base + 3 * H_VEC + c]);

    float4 o;
    o.x = v0 * a.x + v1 * b.x + v2 * d.x + v3 * e.x;
    o.y = v0 * a.y + v1 * b.y + v2 * d.y + v3 * e.y;
    o.z = v0 * a.z + v1 * b.z + v2 * d.z + v3 * e.z;
    o.w = v0 * a.w + v1 * b.w + v2 * d.w + v3 * e.w;

    out[(size_t)r * H_VEC + c] = o;
}

extern "C" void kernel_launch(void* const* d_in, const int* in_sizes, int n_in,
                              void* d_out, int out_size) {
    // metadata order: feats(f32), indices(int), values(f32), num_groups
    const float4* feats  = (const float4*)d_in[0];
    const float*  values = (const float*)d_in[2];
    float4*       out    = (float4*)d_out;

    const int B = 8, G = 1024;
    grouping_kernel<<<B * G, 256>>>(feats, values, out);
}

// round 2
// speedup vs baseline: 1.0011x; 1.0011x over previous
#include <cuda_runtime.h>
#include <cuda_bf16.h>

// Grouping: out[B,G,H] = sum_{t=0..3} values[(b*G+g)*4+t] * feats[b, g*4+t, :]
// B=8, S=4096, H=1024, G=1024, TOKENS_PER_GROUP=4.
// Output row r in [0, B*G) reads feats rows 4r..4r+3 weighted by values[4r..4r+3].
// R2: 2 rows per CTA, 8 batched streaming loads per thread (MLP=8), evict-first hints.

static constexpr int H_VEC = 1024 / 4;   // 256 float4 per row
static constexpr int ROWS_PER_CTA = 2;

__global__ __launch_bounds__(256)
void grouping_kernel(const float4* __restrict__ feats,
                     const float* __restrict__ values,
                     float4* __restrict__ out) {
    const int r0 = blockIdx.x * ROWS_PER_CTA;   // first output row of this CTA
    const int c  = threadIdx.x;                 // float4 column, 0..255

    // weights for both rows (uniform across CTA -> broadcast loads)
    float v[8];
#pragma unroll
    for (int i = 0; i < 8; i++) v[i] = __ldg(&values[4 * r0 + i]);

    // batch all 8 source loads up front: MLP_p1 = 8, streaming (no reuse)
    const size_t base = (size_t)r0 * 4 * H_VEC + c;
    float4 f[8];
#pragma unroll
    for (int t = 0; t < 8; t++)
        f[t] = __ldcs(&feats[base + (size_t)t * H_VEC]);

    float4 o0, o1;
    o0.x = v[0]*f[0].x + v[1]*f[1].x + v[2]*f[2].x + v[3]*f[3].x;
    o0.y = v[0]*f[0].y + v[1]*f[1].y + v[2]*f[2].y + v[3]*f[3].y;
    o0.z = v[0]*f[0].z + v[1]*f[1].z + v[2]*f[2].z + v[3]*f[3].z;
    o0.w = v[0]*f[0].w + v[1]*f[1].w + v[2]*f[2].w + v[3]*f[3].w;

    o1.x = v[4]*f[4].x + v[5]*f[5].x + v[6]*f[6].x + v[7]*f[7].x;
    o1.y = v[4]*f[4].y + v[5]*f[5].y + v[6]*f[6].y + v[7]*f[7].y;
    o1.z = v[4]*f[4].z + v[5]*f[5].z + v[6]*f[6].z + v[7]*f[7].z;
    o1.w = v[4]*f[4].w + v[5]*f[5].w + v[6]*f[6].w + v[7]*f[7].w;

    __stcs(&out[(size_t)r0 * H_VEC + c], o0);
    __stcs(&out[(size_t)(r0 + 1) * H_VEC + c], o1);
}

extern "C" void kernel_launch(void* const* d_in, const int* in_sizes, int n_in,
                              void* d_out, int out_size) {
    // metadata order: feats(f32), indices(int), values(f32), num_groups
    const float4* feats  = (const float4*)d_in[0];
    const float*  values = (const float*)d_in[2];
    float4*       out    = (float4*)d_out;

    const int B = 8, G = 1024;
    grouping_kernel<<<(B * G) / ROWS_PER_CTA, 256>>>(feats, values, out);
}